// round 2
// baseline (speedup 1.0000x reference)
#include <cuda_runtime.h>

#define AHH 8
#define AWW 8
#define ROI_SCALE 0.0625f
#define CCH 256
#define HH 64
#define WW 64

// Block = 256 threads = 8 warps. Each block: one ROI, 8 consecutive channels
// (one channel per warp). Lanes cover the 8x8 sampling grid row-major so
// adjacent lanes hit x-adjacent feature addresses (L2 sector locality).
__global__ __launch_bounds__(256) void roialign_maxpool_kernel(
    const float* __restrict__ feat,
    const float* __restrict__ rois,
    float* __restrict__ out)
{
    __shared__ int   s_iy0[64];
    __shared__ int   s_ix0[64];
    __shared__ float s_ly[64];
    __shared__ float s_lx[64];
    __shared__ unsigned char s_valid[64];
    __shared__ int   s_b;
    __shared__ float s_vals[8][64];   // per-warp 8x8 bin values

    const int roi   = blockIdx.x >> 5;        // 32 blocks per roi (256 ch / 8)
    const int cbase = (blockIdx.x & 31) << 3; // 8 channels per block
    const int tid   = threadIdx.x;

    // ---- per-ROI geometry, computed once by threads 0..63 ----
    if (tid < 64) {
        const float* r = rois + roi * 5;
        const float x1 = r[1] * ROI_SCALE;
        const float y1 = r[2] * ROI_SCALE;
        const float x2 = r[3] * ROI_SCALE;
        const float y2 = r[4] * ROI_SCALE;
        const float bin_h = (y2 - y1) / (float)(AHH - 1);
        const float bin_w = (x2 - x1) / (float)(AWW - 1);
        const int j = tid >> 3;   // y bin
        const int i = tid & 7;    // x bin
        const float ys = y1 + bin_h * (float)j;
        const float xs = x1 + bin_w * (float)i;
        const bool valid = (ys >= 0.0f) && (ys < (float)HH) &&
                           (xs >= 0.0f) && (xs < (float)WW);
        const float y0 = floorf(ys);
        const float x0 = floorf(xs);
        int iy0 = (int)y0; iy0 = min(max(iy0, 0), HH - 1);
        int ix0 = (int)x0; ix0 = min(max(ix0, 0), WW - 1);
        s_iy0[tid]   = iy0;
        s_ix0[tid]   = ix0;
        s_ly[tid]    = ys - y0;
        s_lx[tid]    = xs - x0;
        s_valid[tid] = valid ? 1 : 0;
        if (tid == 0) s_b = (int)r[0];
    }
    __syncthreads();

    const int warp = tid >> 5;
    const int lane = tid & 31;
    const int c    = cbase + warp;
    const float* plane = feat + ((size_t)s_b * CCH + c) * (size_t)(HH * WW);

    // ---- bilinear sampling: 2 bins per lane (row-major bin order) ----
    #pragma unroll
    for (int t = 0; t < 2; t++) {
        const int bin = lane + t * 32;
        const int iy0 = s_iy0[bin];
        const int ix0 = s_ix0[bin];
        const int iy1 = min(iy0 + 1, HH - 1);
        const int ix1 = min(ix0 + 1, WW - 1);
        const float ly = s_ly[bin];
        const float lx = s_lx[bin];
        const float* r0 = plane + iy0 * WW;
        const float* r1 = plane + iy1 * WW;
        const float v00 = __ldg(r0 + ix0);
        const float v01 = __ldg(r0 + ix1);
        const float v10 = __ldg(r1 + ix0);
        const float v11 = __ldg(r1 + ix1);
        const float hy = 1.0f - ly;
        const float hx = 1.0f - lx;
        float v = hy * (hx * v00 + lx * v01) + ly * (hx * v10 + lx * v11);
        s_vals[warp][bin] = s_valid[bin] ? v : 0.0f;
    }
    __syncwarp();

    // ---- fused 2x2/s1 maxpool: 49 outputs per (roi, channel) ----
    float* base_out = out + ((size_t)roi * CCH + c) * 49;
    #pragma unroll
    for (int t = 0; t < 2; t++) {
        const int k = lane + t * 32;
        if (k < 49) {
            const int ph = k / 7;
            const int pw = k - ph * 7;
            const int b0 = ph * 8 + pw;
            const float a = s_vals[warp][b0];
            const float b = s_vals[warp][b0 + 1];
            const float d = s_vals[warp][b0 + 8];
            const float e = s_vals[warp][b0 + 9];
            base_out[k] = fmaxf(fmaxf(a, b), fmaxf(d, e));
        }
    }
}

extern "C" void kernel_launch(void* const* d_in, const int* in_sizes, int n_in,
                              void* d_out, int out_size)
{
    const float* feat = (const float*)d_in[0];  // [4,256,64,64] f32
    const float* rois = (const float*)d_in[1];  // [N,5] f32
    float* out = (float*)d_out;                 // [N,256,7,7] f32
    const int N = in_sizes[1] / 5;
    roialign_maxpool_kernel<<<N * 32, 256>>>(feat, rois, out);
}

// round 3
// speedup vs baseline: 2.1173x; 2.1173x over previous
#include <cuda_runtime.h>

#define CCH 256
#define HH 64
#define WW 64
#define NPIX (HH * WW)

// 4 * 4096 * 256 floats = 16 MB channels-last scratch
__device__ float g_feat_nhwc[4 * NPIX * CCH];

// NCHW -> NHWC transpose: per batch, [C=256][P=4096] -> [P][C]
__global__ __launch_bounds__(256) void transpose_kernel(const float* __restrict__ feat)
{
    __shared__ float tile[32][33];
    const int b  = blockIdx.z;
    const int p0 = blockIdx.x * 32;
    const int c0 = blockIdx.y * 32;
    const int tx = threadIdx.x;
    const int ty = threadIdx.y;
    const float* src = feat + (size_t)b * CCH * NPIX;
    float* dst = g_feat_nhwc + (size_t)b * NPIX * CCH;
#pragma unroll
    for (int i = 0; i < 32; i += 8)
        tile[ty + i][tx] = src[(size_t)(c0 + ty + i) * NPIX + (p0 + tx)];
    __syncthreads();
#pragma unroll
    for (int i = 0; i < 32; i += 8)
        dst[(size_t)(p0 + ty + i) * CCH + (c0 + tx)] = tile[tx][ty + i];
}

// Block = 128 threads (4 warps). Each block: one ROI, 128 channels
// (warp = 32 consecutive channels, lane = channel). Gathers are 128B
// coalesced lines from NHWC scratch; maxpool fused in registers.
__global__ __launch_bounds__(128) void roialign_maxpool_kernel(
    const float* __restrict__ rois,
    float* __restrict__ out)
{
    __shared__ int   s_off[64][4];
    __shared__ float s_w[64][4];
    __shared__ int   s_b;
    __shared__ float s_pool[4][32 * 49];   // [warp][ch][49] == output order

    const int roi  = blockIdx.x >> 1;
    const int half = blockIdx.x & 1;
    const int tid  = threadIdx.x;

    // ---- per-ROI geometry: offsets + weights per bin (valid folded into w) ----
    if (tid < 64) {
        const float* r = rois + (size_t)roi * 5;
        const float x1 = r[1] * 0.0625f;
        const float y1 = r[2] * 0.0625f;
        const float x2 = r[3] * 0.0625f;
        const float y2 = r[4] * 0.0625f;
        const float bh = (y2 - y1) / 7.0f;
        const float bw = (x2 - x1) / 7.0f;
        const int j = tid >> 3;
        const int i = tid & 7;
        const float ys = y1 + bh * (float)j;
        const float xs = x1 + bw * (float)i;
        const bool valid = (ys >= 0.0f) && (ys < (float)HH) &&
                           (xs >= 0.0f) && (xs < (float)WW);
        const float y0 = floorf(ys);
        const float x0 = floorf(xs);
        const float ly = ys - y0;
        const float lx = xs - x0;
        int iy0 = min(max((int)y0, 0), HH - 1);
        int ix0 = min(max((int)x0, 0), WW - 1);
        int iy1 = min(iy0 + 1, HH - 1);
        int ix1 = min(ix0 + 1, WW - 1);
        float hy = 1.0f - ly, hx = 1.0f - lx;
        float w00 = hy * hx, w01 = hy * lx, w10 = ly * hx, w11 = ly * lx;
        if (!valid) { w00 = 0.0f; w01 = 0.0f; w10 = 0.0f; w11 = 0.0f; }
        s_off[tid][0] = (iy0 * WW + ix0) * CCH;
        s_off[tid][1] = (iy0 * WW + ix1) * CCH;
        s_off[tid][2] = (iy1 * WW + ix0) * CCH;
        s_off[tid][3] = (iy1 * WW + ix1) * CCH;
        s_w[tid][0] = w00; s_w[tid][1] = w01; s_w[tid][2] = w10; s_w[tid][3] = w11;
        if (tid == 0) s_b = (int)r[0];
    }
    __syncthreads();

    const int warp  = tid >> 5;
    const int lane  = tid & 31;
    const int cbase = half * 128 + warp * 32;
    const float* p  = g_feat_nhwc + (size_t)s_b * (NPIX * CCH) + cbase + lane;
    float* pool = &s_pool[warp][0];

    float prev[8], cur[8];
#pragma unroll
    for (int j = 0; j < 8; j++) {
#pragma unroll
        for (int i = 0; i < 8; i++) {
            const int bin = j * 8 + i;
            const float v00 = __ldg(p + s_off[bin][0]);
            const float v01 = __ldg(p + s_off[bin][1]);
            const float v10 = __ldg(p + s_off[bin][2]);
            const float v11 = __ldg(p + s_off[bin][3]);
            cur[i] = s_w[bin][0] * v00 + s_w[bin][1] * v01 +
                     s_w[bin][2] * v10 + s_w[bin][3] * v11;
        }
        if (j > 0) {
#pragma unroll
            for (int pw = 0; pw < 7; pw++) {
                const float m = fmaxf(fmaxf(prev[pw], prev[pw + 1]),
                                      fmaxf(cur[pw],  cur[pw + 1]));
                pool[lane * 49 + (j - 1) * 7 + pw] = m;   // stride 49 (odd): conflict-free
            }
        }
#pragma unroll
        for (int i = 0; i < 8; i++) prev[i] = cur[i];
    }
    __syncwarp();

    // ---- coalesced output: warp's 32 channels are 1568 contiguous floats ----
    float* obase = out + ((size_t)roi * CCH + cbase) * 49;
#pragma unroll 7
    for (int idx = lane; idx < 32 * 49; idx += 32)
        obase[idx] = pool[idx];
}

extern "C" void kernel_launch(void* const* d_in, const int* in_sizes, int n_in,
                              void* d_out, int out_size)
{
    const float* feat = (const float*)d_in[0];  // [4,256,64,64] f32
    const float* rois = (const float*)d_in[1];  // [N,5] f32
    float* out = (float*)d_out;                 // [N,256,7,7] f32
    const int N = in_sizes[1] / 5;

    dim3 tb(32, 8);
    dim3 tg(NPIX / 32, CCH / 32, 4);
    transpose_kernel<<<tg, tb>>>(feat);

    roialign_maxpool_kernel<<<N * 2, 128>>>(rois, out);
}